// round 6
// baseline (speedup 1.0000x reference)
#include <cuda_runtime.h>
#include <cuda_bf16.h>
#include <math.h>
#include <stdint.h>

#define B_  2
#define S_  2048
#define D_  1024
#define H_  16
#define HD_ 64
#define M_  (B_*S_)   // 4096

// Pre-split bf16 planes (prep kernels)
__device__ __nv_bfloat16 g_Xh[M_*D_], g_Xl[M_*D_];               // X  [m][k]
__device__ __nv_bfloat16 g_Wth[3*D_*D_], g_Wtl[3*D_*D_];         // Wt [n][k] x3
// Rotated Q/K/V bf16 hi/lo planes, [B,H,S,HD] (Q pre-scaled by 0.125*log2e)
__device__ __nv_bfloat16 g_Qh[B_*H_*S_*HD_], g_Ql[B_*H_*S_*HD_];
__device__ __nv_bfloat16 g_Kh[B_*H_*S_*HD_], g_Kl[B_*H_*S_*HD_];
__device__ __nv_bfloat16 g_Vh[B_*H_*S_*HD_], g_Vl[B_*H_*S_*HD_];

// ===========================================================================
// helpers
// ===========================================================================
__device__ __forceinline__ uint32_t smem_u32(const void* p) {
    uint32_t a;
    asm("{ .reg .u64 t; cvta.to.shared.u64 t, %1; cvt.u32.u64 %0, t; }" : "=r"(a) : "l"(p));
    return a;
}
#define SWZ(off) ((off) ^ (((off) >> 3) & 0x70))

__device__ __forceinline__ void cpa16(uint32_t dst, const void* src) {
    asm volatile("cp.async.cg.shared.global [%0], [%1], 16;" :: "r"(dst), "l"(src));
}
#define CPA_COMMIT() asm volatile("cp.async.commit_group;" ::: "memory")
#define CPA_WAIT(n)  asm volatile("cp.async.wait_group %0;" :: "n"(n) : "memory")

__device__ __forceinline__ void ldm_x4(uint32_t& r0, uint32_t& r1, uint32_t& r2, uint32_t& r3, uint32_t a) {
    asm volatile("ldmatrix.sync.aligned.m8n8.x4.shared.b16 {%0,%1,%2,%3}, [%4];"
                 : "=r"(r0), "=r"(r1), "=r"(r2), "=r"(r3) : "r"(a));
}
__device__ __forceinline__ void ldm_x4t(uint32_t& r0, uint32_t& r1, uint32_t& r2, uint32_t& r3, uint32_t a) {
    asm volatile("ldmatrix.sync.aligned.m8n8.x4.trans.shared.b16 {%0,%1,%2,%3}, [%4];"
                 : "=r"(r0), "=r"(r1), "=r"(r2), "=r"(r3) : "r"(a));
}
__device__ __forceinline__ void mma16816(float* c, const uint32_t* a, uint32_t b0, uint32_t b1) {
    asm volatile(
        "mma.sync.aligned.m16n8k16.row.col.f32.bf16.bf16.f32 "
        "{%0,%1,%2,%3}, {%4,%5,%6,%7}, {%8,%9}, {%0,%1,%2,%3};"
        : "+f"(c[0]), "+f"(c[1]), "+f"(c[2]), "+f"(c[3])
        : "r"(a[0]), "r"(a[1]), "r"(a[2]), "r"(a[3]), "r"(b0), "r"(b1));
}
__device__ __forceinline__ void split_bf16(float x, __nv_bfloat16& h, __nv_bfloat16& l) {
    h = __float2bfloat16(x);
    l = __float2bfloat16(x - __bfloat162float(h));
}
// packed split: (p0,p1) -> hi bf16x2 (lo half = p0) + lo-residual bf16x2
__device__ __forceinline__ void split2(float p0, float p1, uint32_t& hi, uint32_t& lo) {
    asm("cvt.rn.bf16x2.f32 %0, %1, %2;" : "=r"(hi) : "f"(p1), "f"(p0));
    const float f0 = __uint_as_float(hi << 16);
    const float f1 = __uint_as_float(hi & 0xffff0000u);
    asm("cvt.rn.bf16x2.f32 %0, %1, %2;" : "=r"(lo) : "f"(p1 - f1), "f"(p0 - f0));
}
__device__ __forceinline__ float ex2(float x) {
    float y; asm("ex2.approx.f32 %0, %1;" : "=f"(y) : "f"(x)); return y;
}

// ===========================================================================
// Prep 1: split X into bf16 hi/lo planes (same [m][k] layout)
// ===========================================================================
__global__ __launch_bounds__(256) void split_x_kernel(const float* __restrict__ X)
{
    const int i = blockIdx.x * 256 + threadIdx.x;     // float4 index
    float4 v = ((const float4*)X)[i];
    uint32_t h01, l01, h23, l23;
    split2(v.x, v.y, h01, l01);
    split2(v.z, v.w, h23, l23);
    ((uint32_t*)g_Xh)[i*2]   = h01;
    ((uint32_t*)g_Xh)[i*2+1] = h23;
    ((uint32_t*)g_Xl)[i*2]   = l01;
    ((uint32_t*)g_Xl)[i*2+1] = l23;
}

// ===========================================================================
// Prep 2: transpose + split W -> Wt[n][k] hi/lo. 64x64 tiles via smem.
// ===========================================================================
__global__ __launch_bounds__(256) void transw_kernel(
    const float* __restrict__ Wq, const float* __restrict__ Wk, const float* __restrict__ Wv)
{
    __shared__ float tile[64][65];
    const int w = blockIdx.z;
    const float* W = (w == 0) ? Wq : (w == 1 ? Wk : Wv);
    const int k0 = blockIdx.x * 64;
    const int n0 = blockIdx.y * 64;
    const int tid = threadIdx.x;

    #pragma unroll
    for (int it = 0; it < 4; it++) {
        const int idx = it * 256 + tid;
        const int r = idx >> 4, c4 = (idx & 15) << 2;
        float4 v = *(const float4*)&W[(size_t)(k0 + r) * D_ + n0 + c4];
        tile[r][c4] = v.x; tile[r][c4+1] = v.y; tile[r][c4+2] = v.z; tile[r][c4+3] = v.w;
    }
    __syncthreads();
    __nv_bfloat16* Oh = g_Wth + (size_t)w * D_ * D_;
    __nv_bfloat16* Ol = g_Wtl + (size_t)w * D_ * D_;
    #pragma unroll
    for (int it = 0; it < 4; it++) {
        const int idx = it * 256 + tid;
        const int rn = idx >> 4, kc4 = (idx & 15) << 2;
        uint32_t h01, l01, h23, l23;
        split2(tile[kc4 + 0][rn], tile[kc4 + 1][rn], h01, l01);
        split2(tile[kc4 + 2][rn], tile[kc4 + 3][rn], h23, l23);
        const size_t o = (size_t)(n0 + rn) * D_ + k0 + kc4;
        *(uint32_t*)&Oh[o]   = h01;
        *(uint32_t*)&Oh[o+2] = h23;
        *(uint32_t*)&Ol[o]   = l01;
        *(uint32_t*)&Ol[o+2] = l23;
    }
}

// ===========================================================================
// Kernel 1: QKV GEMM, cp.async 2-stage pipeline + RoPE epilogue.
//   Tile 128x64, BK=64 chunks x16. Stage = Ah(16K) Al(16K) Bh(8K) Bl(8K) = 48KB
//   2 stages = 96KB -> 2 CTAs/SM. 8 warps: 4m x 2n, warp tile 32x32.
// ===========================================================================
#define QKV_STAGE 49152
#define QKV_SMEM (2 * QKV_STAGE)
#define LOG2E 1.44269504088896340736f

__global__ __launch_bounds__(256, 2)
void qkv_hmma_kernel(const float* __restrict__ sinT, const float* __restrict__ cosT)
{
    extern __shared__ char smem[];
    const uint32_t sbase = smem_u32(smem);
    const int tid = threadIdx.x;
    const int wid = tid >> 5;
    const int lane = tid & 31;
    const int wm = (wid >> 1) * 32;    // 0,32,64,96
    const int wn = (wid & 1) * 32;     // 0,32

    const int which = blockIdx.z;
    const int bm = blockIdx.y * 128;
    const int bn = blockIdx.x * 64;
    const __nv_bfloat16* Bth = g_Wth + (size_t)which * D_ * D_;
    const __nv_bfloat16* Btl = g_Wtl + (size_t)which * D_ * D_;
    __nv_bfloat16* OutH = (which == 0) ? g_Qh : (which == 1 ? g_Kh : g_Vh);
    __nv_bfloat16* OutL = (which == 0) ? g_Ql : (which == 1 ? g_Kl : g_Vl);
    const float qscale = (which == 0) ? (0.125f * LOG2E) : 1.0f;

    // stage layout: Ah[0,16K) Al[16K,32K) Bh[32K,40K) Bl[40K,48K)
    auto issue = [&](int ch, int st) {
        const uint32_t sb = sbase + st * QKV_STAGE;
        #pragma unroll
        for (int p = 0; p < 2; p++) {
            const __nv_bfloat16* src = p ? g_Xl : g_Xh;
            #pragma unroll
            for (int it = 0; it < 4; it++) {
                const int idx = it * 256 + tid;
                const int row = idx >> 3, ck = idx & 7;
                cpa16(sb + p * 16384 + SWZ((uint32_t)(row * 128 + ck * 16)),
                      src + (size_t)(bm + row) * D_ + ch * 64 + ck * 8);
            }
        }
        #pragma unroll
        for (int p = 0; p < 2; p++) {
            const __nv_bfloat16* src = p ? Btl : Bth;
            #pragma unroll
            for (int it = 0; it < 2; it++) {
                const int idx = it * 256 + tid;
                const int row = idx >> 3, ck = idx & 7;
                cpa16(sb + 32768 + p * 8192 + SWZ((uint32_t)(row * 128 + ck * 16)),
                      src + (size_t)(bn + row) * D_ + ch * 64 + ck * 8);
            }
        }
        CPA_COMMIT();
    };

    float acc[2][4][4];
    #pragma unroll
    for (int i = 0; i < 2; i++)
        #pragma unroll
        for (int j = 0; j < 4; j++)
            #pragma unroll
            for (int k = 0; k < 4; k++) acc[i][j][k] = 0.f;

    issue(0, 0); issue(1, 1);

    for (int ch = 0; ch < 16; ch++) {
        if (ch < 15) { CPA_WAIT(1); } else { CPA_WAIT(0); }
        __syncthreads();

        const int st = ch & 1;
        const uint32_t sAh = sbase + st * QKV_STAGE;
        const uint32_t sAl = sAh + 16384;
        const uint32_t sBh = sAh + 32768;
        const uint32_t sBl = sAh + 40960;

        #pragma unroll
        for (int ks = 0; ks < 4; ks++) {
            const int koff = ks * 32;
            uint32_t ah[2][4], al[2][4];
            #pragma unroll
            for (int mt = 0; mt < 2; mt++) {
                const int row = wm + mt * 16 + (lane & 15);
                const uint32_t byt = (uint32_t)(row * 128 + koff + ((lane >> 4) << 4));
                ldm_x4(ah[mt][0], ah[mt][1], ah[mt][2], ah[mt][3], sAh + SWZ(byt));
                ldm_x4(al[mt][0], al[mt][1], al[mt][2], al[mt][3], sAl + SWZ(byt));
            }
            #pragma unroll
            for (int ntp = 0; ntp < 2; ntp++) {
                const int row = wn + ntp * 16 + (lane & 15);
                const uint32_t byt = (uint32_t)(row * 128 + koff + ((lane >> 4) << 4));
                uint32_t h0,h1,h2,h3, l0,l1,l2,l3;
                ldm_x4(h0, h1, h2, h3, sBh + SWZ(byt));
                ldm_x4(l0, l1, l2, l3, sBl + SWZ(byt));
                #pragma unroll
                for (int mt = 0; mt < 2; mt++) {
                    mma16816(acc[mt][2*ntp],   ah[mt], h0, h2);
                    mma16816(acc[mt][2*ntp],   ah[mt], l0, l2);
                    mma16816(acc[mt][2*ntp],   al[mt], h0, h2);
                    mma16816(acc[mt][2*ntp+1], ah[mt], h1, h3);
                    mma16816(acc[mt][2*ntp+1], ah[mt], l1, l3);
                    mma16816(acc[mt][2*ntp+1], al[mt], h1, h3);
                }
            }
        }
        __syncthreads();
        if (ch + 2 < 16) issue(ch + 2, st);
    }

    // epilogue: RoPE, Q-scale, packed split, write hi/lo planes
    const int g = lane >> 2;
    const int q2 = (lane & 3) * 2;
    #pragma unroll
    for (int mt = 0; mt < 2; mt++) {
        #pragma unroll
        for (int rr = 0; rr < 2; rr++) {
            const int row = bm + wm + mt * 16 + g + rr * 8;
            const int bb = row >> 11;
            const int ss = row & 2047;
            #pragma unroll
            for (int nt = 0; nt < 4; nt++) {
                const int c = bn + wn + nt * 8 + q2;
                const int h = c >> 6;
                const int d = c & 63;
                const float sn = sinT[ss * (HD_/2) + (d >> 1)];
                const float cs = cosT[ss * (HD_/2) + (d >> 1)];
                const float e = acc[mt][nt][rr * 2 + 0];
                const float o = acc[mt][nt][rr * 2 + 1];
                const float wx = (e * cs - o * sn) * qscale;
                const float wy = (o * cs + e * sn) * qscale;
                uint32_t hi, lo;
                split2(wx, wy, hi, lo);
                const size_t ob = ((size_t)(bb * H_ + h) * S_ + ss) * HD_ + d;
                *(uint32_t*)&OutH[ob] = hi;
                *(uint32_t*)&OutL[ob] = lo;
            }
        }
    }
}

// ===========================================================================
// Kernel 2: flash attention, cp.async 2-stage KV pipeline, 2 CTAs/SM.
//   BQ=128 (8 warps x 16 rows), kt tiles of 64. exp2-domain softmax.
// smem: Qh,Ql 16KB each (32KB) + 2 x {Kh,Kl,Vh,Vl 8KB each} (64KB) = 96KB
// ===========================================================================
#define ATT_SMEM (32768 + 2 * 32768)

__global__ __launch_bounds__(256, 2)
void attn_hmma_kernel(float* __restrict__ Out)
{
    extern __shared__ char smem[];
    const uint32_t sbase = smem_u32(smem);
    const int tid = threadIdx.x;
    const int wid = tid >> 5;
    const int lane = tid & 31;
    const int g = lane >> 2;
    const int q2 = (lane & 3) * 2;

    const int q0 = blockIdx.x * 128;
    const int h  = blockIdx.y;
    const int b  = blockIdx.z;
    const size_t hoff = (size_t)(b * H_ + h) * S_ * HD_;
    const __nv_bfloat16* Qhp = g_Qh + hoff;
    const __nv_bfloat16* Qlp = g_Ql + hoff;
    const __nv_bfloat16* planesKV[4] = {g_Kh + hoff, g_Kl + hoff, g_Vh + hoff, g_Vl + hoff};

    auto issueKV = [&](int kt, int st) {
        const uint32_t sb = sbase + 32768 + st * 32768;
        #pragma unroll
        for (int p = 0; p < 4; p++) {
            #pragma unroll
            for (int it = 0; it < 2; it++) {
                const int idx = it * 256 + tid;    // 512 per plane
                const int row = idx >> 3, ck = idx & 7;
                cpa16(sb + p * 8192 + SWZ((uint32_t)(row * 128 + ck * 16)),
                      planesKV[p] + (size_t)(kt * 64 + row) * HD_ + ck * 8);
            }
        }
        CPA_COMMIT();
    };

    // prologue: Q group + KV 0,1
    #pragma unroll
    for (int p = 0; p < 2; p++) {
        const __nv_bfloat16* qp = p ? Qlp : Qhp;
        #pragma unroll
        for (int it = 0; it < 4; it++) {
            const int idx = it * 256 + tid;
            const int row = idx >> 3, ck = idx & 7;
            cpa16(sbase + p * 16384 + SWZ((uint32_t)(row * 128 + ck * 16)),
                  qp + (size_t)(q0 + row) * HD_ + ck * 8);
        }
    }
    CPA_COMMIT();
    issueKV(0, 0); issueKV(1, 1);

    CPA_WAIT(2);           // Q done
    __syncthreads();

    // Q fragments (held in registers for whole kernel)
    uint32_t qh[4][4], ql[4][4];
    #pragma unroll
    for (int ks = 0; ks < 4; ks++) {
        const int row = wid * 16 + (lane & 15);
        const uint32_t byt = (uint32_t)(row * 128 + ks * 32 + ((lane >> 4) << 4));
        ldm_x4(qh[ks][0], qh[ks][1], qh[ks][2], qh[ks][3], sbase + SWZ(byt));
        ldm_x4(ql[ks][0], ql[ks][1], ql[ks][2], ql[ks][3], sbase + 16384 + SWZ(byt));
    }

    float m_[2] = {-INFINITY, -INFINITY};
    float l_[2] = {0.f, 0.f};
    float o_acc[8][4];
    #pragma unroll
    for (int i = 0; i < 8; i++)
        #pragma unroll
        for (int j = 0; j < 4; j++) o_acc[i][j] = 0.f;

    for (int kt = 0; kt < 32; kt++) {
        if (kt < 31) { CPA_WAIT(1); } else { CPA_WAIT(0); }
        __syncthreads();

        const int st = kt & 1;
        const uint32_t sKh = sbase + 32768 + st * 32768;
        const uint32_t sKl = sKh + 8192;
        const uint32_t sVh = sKh + 16384;
        const uint32_t sVl = sKh + 24576;

        // ---- S = Q K^T (log2-domain scores) ----
        float sc[8][4];
        #pragma unroll
        for (int i = 0; i < 8; i++)
            #pragma unroll
            for (int j = 0; j < 4; j++) sc[i][j] = 0.f;

        #pragma unroll
        for (int ks = 0; ks < 4; ks++) {
            #pragma unroll
            for (int ntp = 0; ntp < 4; ntp++) {
                const int row = ntp * 16 + (lane & 15);
                const uint32_t byt = (uint32_t)(row * 128 + ks * 32 + ((lane >> 4) << 4));
                uint32_t h0,h1,h2,h3, l0,l1,l2,l3;
                ldm_x4(h0, h1, h2, h3, sKh + SWZ(byt));
                ldm_x4(l0, l1, l2, l3, sKl + SWZ(byt));
                mma16816(sc[2*ntp],   qh[ks], h0, h2);
                mma16816(sc[2*ntp],   qh[ks], l0, l2);
                mma16816(sc[2*ntp],   ql[ks], h0, h2);
                mma16816(sc[2*ntp+1], qh[ks], h1, h3);
                mma16816(sc[2*ntp+1], qh[ks], l1, l3);
                mma16816(sc[2*ntp+1], ql[ks], h1, h3);
            }
        }

        // ---- online softmax in exp2 domain (quad shuffles; rows warp-local) ----
        #pragma unroll
        for (int tr = 0; tr < 2; tr++) {
            float tmax = -INFINITY;
            #pragma unroll
            for (int nt = 0; nt < 8; nt++)
                tmax = fmaxf(tmax, fmaxf(sc[nt][tr*2], sc[nt][tr*2+1]));
            tmax = fmaxf(tmax, __shfl_xor_sync(0xffffffffu, tmax, 1));
            tmax = fmaxf(tmax, __shfl_xor_sync(0xffffffffu, tmax, 2));
            const float mnew = fmaxf(m_[tr], tmax);
            const float corr = ex2(m_[tr] - mnew);
            m_[tr] = mnew;
            float rs = 0.f;
            #pragma unroll
            for (int nt = 0; nt < 8; nt++) {
                const float p0 = ex2(sc[nt][tr*2]   - mnew);
                const float p1 = ex2(sc[nt][tr*2+1] - mnew);
                sc[nt][tr*2] = p0; sc[nt][tr*2+1] = p1;
                rs += p0 + p1;
            }
            rs += __shfl_xor_sync(0xffffffffu, rs, 1);
            rs += __shfl_xor_sync(0xffffffffu, rs, 2);
            l_[tr] = l_[tr] * corr + rs;
            #pragma unroll
            for (int dt = 0; dt < 8; dt++) {
                o_acc[dt][tr*2]   *= corr;
                o_acc[dt][tr*2+1] *= corr;
            }
        }

        // ---- O += P V (P packed-split in regs; V frags via trans x4) ----
        #pragma unroll
        for (int ks2 = 0; ks2 < 4; ks2++) {
            uint32_t aHf[4], aLf[4];
            split2(sc[2*ks2][0],   sc[2*ks2][1],   aHf[0], aLf[0]);
            split2(sc[2*ks2][2],   sc[2*ks2][3],   aHf[1], aLf[1]);
            split2(sc[2*ks2+1][0], sc[2*ks2+1][1], aHf[2], aLf[2]);
            split2(sc[2*ks2+1][2], sc[2*ks2+1][3], aHf[3], aLf[3]);
            #pragma unroll
            for (int dtp = 0; dtp < 4; dtp++) {
                const int row = ks2 * 16 + (lane & 15);
                const uint32_t byt = (uint32_t)(row * 128 + dtp * 32 + ((lane >> 4) << 4));
                uint32_t vh0,vh1,vh2,vh3, vl0,vl1,vl2,vl3;
                ldm_x4t(vh0, vh1, vh2, vh3, sVh + SWZ(byt));
                ldm_x4t(vl0, vl1, vl2, vl3, sVl + SWZ(byt));
                mma16816(o_acc[2*dtp],   aHf, vh0, vh1);
                mma16816(o_acc[2*dtp],   aHf, vl0, vl1);
                mma16816(o_acc[2*dtp],   aLf, vh0, vh1);
                mma16816(o_acc[2*dtp+1], aHf, vh2, vh3);
                mma16816(o_acc[2*dtp+1], aHf, vl2, vl3);
                mma16816(o_acc[2*dtp+1], aLf, vh2, vh3);
            }
        }
        __syncthreads();
        if (kt + 2 < 32) issueKV(kt + 2, st);
    }

    // ---- epilogue ----
    #pragma unroll
    for (int tr = 0; tr < 2; tr++) {
        const int qrow = q0 + wid * 16 + g + tr * 8;
        const float inv = 1.f / l_[tr];
        #pragma unroll
        for (int dt = 0; dt < 8; dt++) {
            float2 w;
            w.x = o_acc[dt][tr*2]   * inv;
            w.y = o_acc[dt][tr*2+1] * inv;
            *(float2*)&Out[((size_t)b * S_ + qrow) * D_ + h * HD_ + dt * 8 + q2] = w;
        }
    }
}

// ---------------------------------------------------------------------------
extern "C" void kernel_launch(void* const* d_in, const int* in_sizes, int n_in,
                              void* d_out, int out_size)
{
    const float* X  = (const float*)d_in[0];
    const float* Wq = (const float*)d_in[1];
    const float* Wk = (const float*)d_in[2];
    const float* Wv = (const float*)d_in[3];
    const float* sn = (const float*)d_in[4];
    const float* cs = (const float*)d_in[5];
    float* out = (float*)d_out;

    split_x_kernel<<<M_ * D_ / 4 / 256, 256>>>(X);
    dim3 gw(16, 16, 3);
    transw_kernel<<<gw, 256>>>(Wq, Wk, Wv);

    cudaFuncSetAttribute(qkv_hmma_kernel, cudaFuncAttributeMaxDynamicSharedMemorySize, QKV_SMEM);
    dim3 g1(D_ / 64, M_ / 128, 3);   // (16, 32, 3)
    qkv_hmma_kernel<<<g1, 256, QKV_SMEM>>>(sn, cs);

    cudaFuncSetAttribute(attn_hmma_kernel, cudaFuncAttributeMaxDynamicSharedMemorySize, ATT_SMEM);
    dim3 g2(S_ / 128, H_, B_);       // (16, 16, 2)
    attn_hmma_kernel<<<g2, 256, ATT_SMEM>>>(out);
}